// round 10
// baseline (speedup 1.0000x reference)
#include <cuda_runtime.h>
#include <cuda_fp16.h>
#include <math.h>
#include <stdint.h>

#define BB 8
#define SS 2048
#define HH 768
#define NT (BB*SS)

/* ---------------- device scratch (no allocations allowed) ---------------- */
__device__ float g_ang[NT * 8];
__device__ float g_Qv[NT * 4];     /* pre-scaled by log2(e) */
__device__ float g_Kv[NT * 4];
__device__ float g_rinv[NT];
__device__ __align__(16) __half g_Ph[(size_t)BB * SS * SS];   /* 67 MB: exp(Qv.Kv^T), k-permuted fp16 */
__device__ __align__(16) __half g_Vth[(size_t)BB * HH * SS];  /* 25 MB: emb^T, k-permuted fp16 */

/* ---------------- helpers ---------------- */
__device__ __forceinline__ uint32_t smem_u32(const void* p) {
    uint32_t a;
    asm("{ .reg .u64 t; cvta.to.shared.u64 t, %1; cvt.u32.u64 %0, t; }" : "=r"(a) : "l"(p));
    return a;
}
__device__ __forceinline__ float ex2f(float x) {
    float y; asm("ex2.approx.ftz.f32 %0, %1;" : "=f"(y) : "f"(x)); return y;
}
__device__ __forceinline__ void cpasync16(uint32_t dst, const void* src) {
    asm volatile("cp.async.cg.shared.global [%0], [%1], 16;" :: "r"(dst), "l"(src) : "memory");
}
__device__ __forceinline__ void cp_commit() { asm volatile("cp.async.commit_group;" ::: "memory"); }
template <int N> __device__ __forceinline__ void cp_wait() {
    asm volatile("cp.async.wait_group %0;" :: "n"(N) : "memory");
}
/* fp32-accumulate fp16 mma */
__device__ __forceinline__ void mma_f16(float& c0, float& c1, float& c2, float& c3,
                                        uint32_t a0, uint32_t a1, uint32_t a2, uint32_t a3,
                                        uint32_t b0, uint32_t b1)
{
    asm volatile(
        "mma.sync.aligned.m16n8k16.row.col.f32.f16.f16.f32 "
        "{%0,%1,%2,%3}, {%4,%5,%6,%7}, {%8,%9}, {%0,%1,%2,%3};"
        : "+f"(c0), "+f"(c1), "+f"(c2), "+f"(c3)
        : "r"(a0), "r"(a1), "r"(a2), "r"(a3), "r"(b0), "r"(b1));
}

/* =====================  1) Q/K projection: warp per token ===================== */
__global__ void __launch_bounds__(256) proj_kernel(
    const float* __restrict__ emb,
    const float* __restrict__ Wq, const float* __restrict__ bq,
    const float* __restrict__ Wk, const float* __restrict__ bk)
{
    const int w    = (blockIdx.x * blockDim.x + threadIdx.x) >> 5;
    const int lane = threadIdx.x & 31;

    const float4* e  = (const float4*)(emb + (size_t)w * HH);
    const float4* wq = (const float4*)Wq;
    const float4* wk = (const float4*)Wk;

    float acc[8];
#pragma unroll
    for (int j = 0; j < 8; j++) acc[j] = 0.f;

#pragma unroll
    for (int k = 0; k < 6; k++) {
        const int idx = lane + 32 * k;
        float4 ev = e[idx];
#pragma unroll
        for (int q = 0; q < 4; q++) {
            float4 a = wq[q * 192 + idx];
            acc[q]     += ev.x * a.x + ev.y * a.y + ev.z * a.z + ev.w * a.w;
            float4 c = wk[q * 192 + idx];
            acc[4 + q] += ev.x * c.x + ev.y * c.y + ev.z * c.z + ev.w * c.w;
        }
    }
#pragma unroll
    for (int off = 16; off > 0; off >>= 1)
#pragma unroll
        for (int j = 0; j < 8; j++) acc[j] += __shfl_xor_sync(0xffffffffu, acc[j], off);

    if (lane == 0) {
        float* dst = g_ang + (size_t)w * 8;
#pragma unroll
        for (int q = 0; q < 4; q++) {
            dst[q]     = acc[q] + bq[q];
            dst[4 + q] = acc[4 + q] + bk[q];
        }
    }
}

/* =====================  2) VQC: thread per token ===================== */
__device__ __forceinline__ void vqc_eval(float x0, float x1, float x2, float x3,
                                         const float* rot, float* outz)
{
    float c[4], s[4];
    c[0] = cosf(0.5f * x0); s[0] = sinf(0.5f * x0);
    c[1] = cosf(0.5f * x1); s[1] = sinf(0.5f * x1);
    c[2] = cosf(0.5f * x2); s[2] = sinf(0.5f * x2);
    c[3] = cosf(0.5f * x3); s[3] = sinf(0.5f * x3);

    float pr[16], pi[16];
#pragma unroll
    for (int bb = 0; bb < 16; bb++) {
        float m = ((bb & 8) ? s[0] : c[0]) * ((bb & 4) ? s[1] : c[1]) *
                  ((bb & 2) ? s[2] : c[2]) * ((bb & 1) ? s[3] : c[3]);
        const int k = __popc(bb) & 3;
        pr[bb] = (k == 0) ? m : ((k == 2) ? -m : 0.f);
        pi[bb] = (k == 1) ? -m : ((k == 3) ? m : 0.f);
    }

#pragma unroll
    for (int l = 0; l < 2; l++) {
#pragma unroll
        for (int q = 0; q < 4; q++) {
            const float* g = rot + (l * 4 + q) * 8;
            const float ar = g[0], ai = g[1], br = g[2], bi = g[3];
            const float cr = g[4], ci = g[5], dr = g[6], di = g[7];
            const int mask = 8 >> q;
#pragma unroll
            for (int b0 = 0; b0 < 16; b0++) {
                if (!(b0 & mask)) {
                    const int b1 = b0 | mask;
                    float p0r = pr[b0], p0i = pi[b0], p1r = pr[b1], p1i = pi[b1];
                    pr[b0] = ar * p0r - ai * p0i + br * p1r - bi * p1i;
                    pi[b0] = ar * p0i + ai * p0r + br * p1i + bi * p1r;
                    pr[b1] = cr * p0r - ci * p0i + dr * p1r - di * p1i;
                    pi[b1] = cr * p0i + ci * p0r + dr * p1i + di * p1r;
                }
            }
        }
        const int r = (l % 3) + 1;
#pragma unroll
        for (int i = 0; i < 4; i++) {
            const int cm = 8 >> i;
            const int tm = 8 >> ((i + r) & 3);
#pragma unroll
            for (int b0 = 0; b0 < 16; b0++) {
                if ((b0 & cm) && !(b0 & tm)) {
                    const int b1 = b0 | tm;
                    float tr = pr[b0]; pr[b0] = pr[b1]; pr[b1] = tr;
                    float ti = pi[b0]; pi[b0] = pi[b1]; pi[b1] = ti;
                }
            }
        }
    }

    float z0 = 0.f, z1 = 0.f, z2 = 0.f, z3 = 0.f;
#pragma unroll
    for (int bb = 0; bb < 16; bb++) {
        const float p = pr[bb] * pr[bb] + pi[bb] * pi[bb];
        z0 += (bb & 8) ? -p : p;
        z1 += (bb & 4) ? -p : p;
        z2 += (bb & 2) ? -p : p;
        z3 += (bb & 1) ? -p : p;
    }
    outz[0] = z0; outz[1] = z1; outz[2] = z2; outz[3] = z3;
}

__global__ void __launch_bounds__(128) vqc_kernel(const float* __restrict__ wts)
{
    const int t = blockIdx.x * blockDim.x + threadIdx.x;

    float rot[64];
#pragma unroll
    for (int l = 0; l < 2; l++) {
#pragma unroll
        for (int q = 0; q < 4; q++) {
            const float phi = wts[(l * 4 + q) * 3 + 0];
            const float th  = wts[(l * 4 + q) * 3 + 1];
            const float om  = wts[(l * 4 + q) * 3 + 2];
            const float ct = cosf(0.5f * th), st = sinf(0.5f * th);
            float spo, cpo; sincosf(0.5f * (phi + om), &spo, &cpo);
            float smo, cmo; sincosf(0.5f * (phi - om), &smo, &cmo);
            float* g = rot + (l * 4 + q) * 8;
            g[0] =  cpo * ct; g[1] = -spo * ct;
            g[2] = -cmo * st; g[3] = -smo * st;
            g[4] =  cmo * st; g[5] = -smo * st;
            g[6] =  cpo * ct; g[7] =  spo * ct;
        }
    }

    const float* a = g_ang + (size_t)t * 8;
    float zq[4];
    vqc_eval(a[0], a[1], a[2], a[3], rot, zq);
    /* pre-scale Q by log2(e): scores then use ex2 directly */
    float* qo = g_Qv + (size_t)t * 4;
#pragma unroll
    for (int j = 0; j < 4; j++) qo[j] = zq[j] * 1.4426950408889634f;
    vqc_eval(a[4], a[5], a[6], a[7], rot, g_Kv + (size_t)t * 4);
}

/* =====================  3) V transpose -> fp16, k(t)-permuted in 16-blocks ===================== */
__global__ void __launch_bounds__(256) transpose_kernel(const float* __restrict__ emb)
{
    __shared__ float tile[32][33];
    const int b  = blockIdx.z;
    const int t0 = blockIdx.x * 32;
    const int h0 = blockIdx.y * 32;
    const int tid = threadIdx.y * 32 + threadIdx.x;
    const int tx = threadIdx.x, ty = threadIdx.y;

#pragma unroll
    for (int j = 0; j < 4; j++)
        tile[ty + j * 8][tx] = emb[((size_t)b * SS + t0 + ty + j * 8) * HH + h0 + tx];
    __syncthreads();

    const int hy = tid & 31;
    const int q  = tid >> 5;
    const int blk = q >> 2;
    const int tq  = q & 3;

    const int base = blk * 16;
    __half h[4];
    h[0] = __float2half_rn(tile[base + 2 * tq][hy]);
    h[1] = __float2half_rn(tile[base + 2 * tq + 1][hy]);
    h[2] = __float2half_rn(tile[base + 2 * tq + 8][hy]);
    h[3] = __float2half_rn(tile[base + 2 * tq + 9][hy]);

    *(uint2*)(g_Vth + ((size_t)b * HH + h0 + hy) * SS + t0 + base + 4 * tq) = *(uint2*)h;
}

/* =====================  4) P = exp(Qv Kv^T): 32 rows/CTA, warp-uniform key segment ===================== */
/* 256 threads: row = tid&31 (varies per lane), sub = tid>>5 (constant per warp).
   All lanes of a warp read the same sKv[t] -> LDS broadcast, conflict-free.
   512 CTAs -> ~3.5 CTAs/SM for latency hiding. */
__global__ void __launch_bounds__(256) scoreexp_kernel()
{
    __shared__ float4 sKv[SS];          /* 32 KB */
    __shared__ float sRs[256];
    const int b   = blockIdx.y;
    const int tid = threadIdx.x;
    const int row = tid & 31;
    const int sub = tid >> 5;           /* 0..7: 256 keys each */
    const int s   = blockIdx.x * 32 + row;

    const float4* Kvb = (const float4*)(g_Kv + (size_t)b * SS * 4);
#pragma unroll
    for (int j = 0; j < 8; j++) sKv[tid + j * 256] = Kvb[tid + j * 256];
    __syncthreads();

    const float4 qv = ((const float4*)g_Qv)[(size_t)b * SS + s];   /* pre-scaled by log2e */
    __half* Prow = g_Ph + ((size_t)b * SS + s) * SS;
    float rsum = 0.f;

#pragma unroll 2
    for (int kb = 0; kb < 16; kb++) {
        const int base = sub * 256 + kb * 16;
        float e[16];
#pragma unroll
        for (int j = 0; j < 16; j++) {
            float4 kv = sKv[base + j];          /* warp-uniform address: broadcast */
            e[j] = ex2f(qv.x * kv.x + qv.y * kv.y + qv.z * kv.z + qv.w * kv.w);
        }
#pragma unroll
        for (int j = 0; j < 16; j++) rsum += e[j];
        /* k-permuted fp16 pack: pos 4t+{0,1,2,3} <- e{2t,2t+1,2t+8,2t+9} */
        __half2 h2[8];
        h2[0] = __floats2half2_rn(e[0],  e[1]);
        h2[1] = __floats2half2_rn(e[8],  e[9]);
        h2[2] = __floats2half2_rn(e[2],  e[3]);
        h2[3] = __floats2half2_rn(e[10], e[11]);
        h2[4] = __floats2half2_rn(e[4],  e[5]);
        h2[5] = __floats2half2_rn(e[12], e[13]);
        h2[6] = __floats2half2_rn(e[6],  e[7]);
        h2[7] = __floats2half2_rn(e[14], e[15]);
        uint4* dst = (uint4*)(Prow + base);
        dst[0] = *(uint4*)&h2[0];
        dst[1] = *(uint4*)&h2[4];
    }

    sRs[tid] = rsum;
    __syncthreads();
    if (tid < 32) {
        float r = 0.f;
#pragma unroll
        for (int k = 0; k < 8; k++) r += sRs[tid + k * 32];
        g_rinv[(size_t)b * SS + blockIdx.x * 32 + tid] = 1.0f / r;
    }
}

/* =====================  5) fp16 mma.sync GEMM (fp32 acc): O = (P @ Vt^T) * rinv ===================== */
#define GM 128
#define GN 128
#define GK 32                     /* halves per k-chunk */
#define NCH (SS / GK)             /* 64 */
#define PITCH 40                  /* halves per smem row: 32 data + 8 pad */
#define A_HALVES (GM * PITCH)     /* 5120 (10240 B) */
#define B_HALVES (GN * PITCH)     /* 5120 (10240 B) */
#define STAGE_HALVES (A_HALVES + B_HALVES)   /* 10240 halves = 20480 B */
#define STAGES 4                  /* 4 buffers, 3 chunks in flight -> one barrier per chunk */
#define GTHREADS 128

__device__ __forceinline__ void load_chunk(uint32_t sA, uint32_t sB,
                                           const __half* __restrict__ Pb,
                                           const __half* __restrict__ Vtb,
                                           int m0, int n0, int k0, int tid)
{
#pragma unroll
    for (int j = 0; j < 4; j++) {                    /* A: 128 rows x 4 x 16B */
        const int cid = tid + j * GTHREADS;
        const int r = cid >> 2, c = cid & 3;
        cpasync16(sA + (r * PITCH + c * 8) * 2, Pb + (size_t)(m0 + r) * SS + k0 + c * 8);
    }
#pragma unroll
    for (int j = 0; j < 4; j++) {                    /* B: 128 rows x 4 x 16B */
        const int cid = tid + j * GTHREADS;
        const int r = cid >> 2, c = cid & 3;
        cpasync16(sB + (r * PITCH + c * 8) * 2, Vtb + (size_t)(n0 + r) * SS + k0 + c * 8);
    }
    cp_commit();
}

__global__ void __launch_bounds__(GTHREADS, 2) gemm_kernel(float* __restrict__ out)
{
    extern __shared__ __align__(16) __half hsm[];
    const uint32_t smem_base = smem_u32(hsm);
    const int tid  = threadIdx.x;
    const int wid  = tid >> 5;
    const int lane = tid & 31;
    const int g = lane >> 2;
    const int t = lane & 3;

    const int wm = wid & 1;           /* 64-row block */
    const int wn = (wid >> 1) & 1;    /* 64-col block */

    const int b  = blockIdx.y;
    const int nt = blockIdx.x % 6;
    const int mt = blockIdx.x / 6;
    const int m0 = mt * GM;
    const int n0 = nt * GN;

    const __half* Pb  = g_Ph  + (size_t)b * SS * SS;
    const __half* Vtb = g_Vth + (size_t)b * HH * SS;

    float acc[4][8][4];
#pragma unroll
    for (int i = 0; i < 4; i++)
#pragma unroll
        for (int j = 0; j < 8; j++)
#pragma unroll
            for (int k = 0; k < 4; k++) acc[i][j][k] = 0.f;

    const int aBase = (wm * 64 + g) * PITCH + 4 * t;
    const int bBase = (wn * 64 + g) * PITCH + 4 * t;

    /* prologue: 3 chunks in flight */
#pragma unroll
    for (int i = 0; i < 3; i++)
        load_chunk(smem_base + (i * STAGE_HALVES) * 2,
                   smem_base + (i * STAGE_HALVES + A_HALVES) * 2,
                   Pb, Vtb, m0, n0, i * GK, tid);

    for (int i = 0; i < NCH; i++) {
        if (i < NCH - 2)      cp_wait<2>();
        else if (i == NCH - 2) cp_wait<1>();
        else                  cp_wait<0>();
        __syncthreads();   /* chunk i visible to all; prior-iter LDS complete before overwrite */

        if (i + 3 < NCH) {
            const int st = (i + 3) & 3;
            load_chunk(smem_base + (st * STAGE_HALVES) * 2,
                       smem_base + (st * STAGE_HALVES + A_HALVES) * 2,
                       Pb, Vtb, m0, n0, (i + 3) * GK, tid);
        }

        const __half* sA = hsm + (i & 3) * STAGE_HALVES;
        const __half* sB = sA + A_HALVES;

#pragma unroll
        for (int ks = 0; ks < 2; ks++) {
            uint2 aG[4], aG8[4], bF[8];
#pragma unroll
            for (int ti = 0; ti < 4; ti++) {
                aG[ti]  = *(const uint2*)(sA + aBase + ti * 16 * PITCH + ks * 16);
                aG8[ti] = *(const uint2*)(sA + aBase + (ti * 16 + 8) * PITCH + ks * 16);
            }
#pragma unroll
            for (int tj = 0; tj < 8; tj++)
                bF[tj] = *(const uint2*)(sB + bBase + tj * 8 * PITCH + ks * 16);
#pragma unroll
            for (int ti = 0; ti < 4; ti++)
#pragma unroll
                for (int tj = 0; tj < 8; tj++)
                    mma_f16(acc[ti][tj][0], acc[ti][tj][1], acc[ti][tj][2], acc[ti][tj][3],
                            aG[ti].x, aG8[ti].x, aG[ti].y, aG8[ti].y,
                            bF[tj].x, bF[tj].y);
        }
        /* no trailing sync: with 4 stages and 3 in flight, the next overwrite
           target was consumed a full iteration ago; top-of-loop sync orders it */
    }

    /* epilogue */
    const float* rinvB = g_rinv + (size_t)b * SS + m0 + wm * 64;
    float* outB = out + ((size_t)b * SS + m0 + wm * 64) * HH + n0 + wn * 64;
#pragma unroll
    for (int ti = 0; ti < 4; ti++) {
        const int r0 = ti * 16 + g;
        const float ri0 = rinvB[r0];
        const float ri1 = rinvB[r0 + 8];
#pragma unroll
        for (int tj = 0; tj < 8; tj++) {
            const int c0 = tj * 8 + 2 * t;
            float2 v0 = make_float2(acc[ti][tj][0] * ri0, acc[ti][tj][1] * ri0);
            float2 v1 = make_float2(acc[ti][tj][2] * ri1, acc[ti][tj][3] * ri1);
            *(float2*)(outB + (size_t)r0 * HH + c0) = v0;
            *(float2*)(outB + (size_t)(r0 + 8) * HH + c0) = v1;
        }
    }
}

/* =====================  launch ===================== */
extern "C" void kernel_launch(void* const* d_in, const int* in_sizes, int n_in,
                              void* d_out, int out_size)
{
    const float* emb = (const float*)d_in[0];
    const float* Wq  = (const float*)d_in[1];
    const float* bq  = (const float*)d_in[2];
    const float* Wk  = (const float*)d_in[3];
    const float* bk  = (const float*)d_in[4];
    const float* wts = (const float*)d_in[5];
    float* out = (float*)d_out;

    /* lazily created side stream + events (host resources, created once on the
       first (non-capture) call; per-call work is identical and deterministic) */
    static cudaStream_t s2 = nullptr;
    static cudaEvent_t evFork = nullptr, evJoin = nullptr;
    if (s2 == nullptr) {
        cudaStreamCreateWithFlags(&s2, cudaStreamNonBlocking);
        cudaEventCreateWithFlags(&evFork, cudaEventDisableTiming);
        cudaEventCreateWithFlags(&evJoin, cudaEventDisableTiming);
    }

    /* fork: transpose depends only on emb -> run it parallel to proj/vqc/scoreexp */
    cudaEventRecord(evFork, 0);
    cudaStreamWaitEvent(s2, evFork, 0);
    transpose_kernel<<<dim3(SS / 32, HH / 32, BB), dim3(32, 8), 0, s2>>>(emb);
    cudaEventRecord(evJoin, s2);

    proj_kernel<<<NT / 8, 256>>>(emb, Wq, bq, Wk, bk);
    vqc_kernel<<<NT / 128, 128>>>(wts);
    scoreexp_kernel<<<dim3(SS / 32, BB), 256>>>();

    /* join before GEMM (needs g_Vth) */
    cudaStreamWaitEvent(0, evJoin, 0);

    const int smem = STAGES * STAGE_HALVES * 2;          /* 81920 B */
    cudaFuncSetAttribute(gemm_kernel, cudaFuncAttributeMaxDynamicSharedMemorySize, smem);
    gemm_kernel<<<dim3((SS / GM) * (HH / GN), BB), GTHREADS, smem>>>(out);
}

// round 11
// speedup vs baseline: 1.4933x; 1.4933x over previous
#include <cuda_runtime.h>
#include <cuda_fp16.h>
#include <math.h>
#include <stdint.h>

#define BB 8
#define SS 2048
#define HH 768
#define NT (BB*SS)

/* ---------------- device scratch (no allocations allowed) ---------------- */
__device__ float g_ang[NT * 8];
__device__ float g_Qv[NT * 4];     /* pre-scaled by log2(e) */
__device__ float g_Kv[NT * 4];
__device__ float g_rinv[NT];
__device__ __align__(16) __half g_Ph[(size_t)BB * SS * SS];   /* 67 MB: exp(Qv.Kv^T), k-permuted fp16 */
__device__ __align__(16) __half g_Vth[(size_t)BB * HH * SS];  /* 25 MB: emb^T, k-permuted fp16 */

/* ---------------- helpers ---------------- */
__device__ __forceinline__ uint32_t smem_u32(const void* p) {
    uint32_t a;
    asm("{ .reg .u64 t; cvta.to.shared.u64 t, %1; cvt.u32.u64 %0, t; }" : "=r"(a) : "l"(p));
    return a;
}
__device__ __forceinline__ float ex2f(float x) {
    float y; asm("ex2.approx.ftz.f32 %0, %1;" : "=f"(y) : "f"(x)); return y;
}
__device__ __forceinline__ void cpasync16(uint32_t dst, const void* src) {
    asm volatile("cp.async.cg.shared.global [%0], [%1], 16;" :: "r"(dst), "l"(src) : "memory");
}
__device__ __forceinline__ void cp_commit() { asm volatile("cp.async.commit_group;" ::: "memory"); }
template <int N> __device__ __forceinline__ void cp_wait() {
    asm volatile("cp.async.wait_group %0;" :: "n"(N) : "memory");
}
/* fp32-accumulate fp16 mma */
__device__ __forceinline__ void mma_f16(float& c0, float& c1, float& c2, float& c3,
                                        uint32_t a0, uint32_t a1, uint32_t a2, uint32_t a3,
                                        uint32_t b0, uint32_t b1)
{
    asm volatile(
        "mma.sync.aligned.m16n8k16.row.col.f32.f16.f16.f32 "
        "{%0,%1,%2,%3}, {%4,%5,%6,%7}, {%8,%9}, {%0,%1,%2,%3};"
        : "+f"(c0), "+f"(c1), "+f"(c2), "+f"(c3)
        : "r"(a0), "r"(a1), "r"(a2), "r"(a3), "r"(b0), "r"(b1));
}

/* =====================  1) Q/K projection: warp per token ===================== */
__global__ void __launch_bounds__(256) proj_kernel(
    const float* __restrict__ emb,
    const float* __restrict__ Wq, const float* __restrict__ bq,
    const float* __restrict__ Wk, const float* __restrict__ bk)
{
    const int w    = (blockIdx.x * blockDim.x + threadIdx.x) >> 5;
    const int lane = threadIdx.x & 31;

    const float4* e  = (const float4*)(emb + (size_t)w * HH);
    const float4* wq = (const float4*)Wq;
    const float4* wk = (const float4*)Wk;

    float acc[8];
#pragma unroll
    for (int j = 0; j < 8; j++) acc[j] = 0.f;

#pragma unroll
    for (int k = 0; k < 6; k++) {
        const int idx = lane + 32 * k;
        float4 ev = e[idx];
#pragma unroll
        for (int q = 0; q < 4; q++) {
            float4 a = wq[q * 192 + idx];
            acc[q]     += ev.x * a.x + ev.y * a.y + ev.z * a.z + ev.w * a.w;
            float4 c = wk[q * 192 + idx];
            acc[4 + q] += ev.x * c.x + ev.y * c.y + ev.z * c.z + ev.w * c.w;
        }
    }
#pragma unroll
    for (int off = 16; off > 0; off >>= 1)
#pragma unroll
        for (int j = 0; j < 8; j++) acc[j] += __shfl_xor_sync(0xffffffffu, acc[j], off);

    if (lane == 0) {
        float* dst = g_ang + (size_t)w * 8;
#pragma unroll
        for (int q = 0; q < 4; q++) {
            dst[q]     = acc[q] + bq[q];
            dst[4 + q] = acc[4 + q] + bk[q];
        }
    }
}

/* =====================  2) VQC: thread per token ===================== */
__device__ __forceinline__ void vqc_eval(float x0, float x1, float x2, float x3,
                                         const float* rot, float* outz)
{
    float c[4], s[4];
    c[0] = cosf(0.5f * x0); s[0] = sinf(0.5f * x0);
    c[1] = cosf(0.5f * x1); s[1] = sinf(0.5f * x1);
    c[2] = cosf(0.5f * x2); s[2] = sinf(0.5f * x2);
    c[3] = cosf(0.5f * x3); s[3] = sinf(0.5f * x3);

    float pr[16], pi[16];
#pragma unroll
    for (int bb = 0; bb < 16; bb++) {
        float m = ((bb & 8) ? s[0] : c[0]) * ((bb & 4) ? s[1] : c[1]) *
                  ((bb & 2) ? s[2] : c[2]) * ((bb & 1) ? s[3] : c[3]);
        const int k = __popc(bb) & 3;
        pr[bb] = (k == 0) ? m : ((k == 2) ? -m : 0.f);
        pi[bb] = (k == 1) ? -m : ((k == 3) ? m : 0.f);
    }

#pragma unroll
    for (int l = 0; l < 2; l++) {
#pragma unroll
        for (int q = 0; q < 4; q++) {
            const float* g = rot + (l * 4 + q) * 8;
            const float ar = g[0], ai = g[1], br = g[2], bi = g[3];
            const float cr = g[4], ci = g[5], dr = g[6], di = g[7];
            const int mask = 8 >> q;
#pragma unroll
            for (int b0 = 0; b0 < 16; b0++) {
                if (!(b0 & mask)) {
                    const int b1 = b0 | mask;
                    float p0r = pr[b0], p0i = pi[b0], p1r = pr[b1], p1i = pi[b1];
                    pr[b0] = ar * p0r - ai * p0i + br * p1r - bi * p1i;
                    pi[b0] = ar * p0i + ai * p0r + br * p1i + bi * p1r;
                    pr[b1] = cr * p0r - ci * p0i + dr * p1r - di * p1i;
                    pi[b1] = cr * p0i + ci * p0r + dr * p1i + di * p1r;
                }
            }
        }
        const int r = (l % 3) + 1;
#pragma unroll
        for (int i = 0; i < 4; i++) {
            const int cm = 8 >> i;
            const int tm = 8 >> ((i + r) & 3);
#pragma unroll
            for (int b0 = 0; b0 < 16; b0++) {
                if ((b0 & cm) && !(b0 & tm)) {
                    const int b1 = b0 | tm;
                    float tr = pr[b0]; pr[b0] = pr[b1]; pr[b1] = tr;
                    float ti = pi[b0]; pi[b0] = pi[b1]; pi[b1] = ti;
                }
            }
        }
    }

    float z0 = 0.f, z1 = 0.f, z2 = 0.f, z3 = 0.f;
#pragma unroll
    for (int bb = 0; bb < 16; bb++) {
        const float p = pr[bb] * pr[bb] + pi[bb] * pi[bb];
        z0 += (bb & 8) ? -p : p;
        z1 += (bb & 4) ? -p : p;
        z2 += (bb & 2) ? -p : p;
        z3 += (bb & 1) ? -p : p;
    }
    outz[0] = z0; outz[1] = z1; outz[2] = z2; outz[3] = z3;
}

__global__ void __launch_bounds__(128) vqc_kernel(const float* __restrict__ wts)
{
    const int t = blockIdx.x * blockDim.x + threadIdx.x;

    float rot[64];
#pragma unroll
    for (int l = 0; l < 2; l++) {
#pragma unroll
        for (int q = 0; q < 4; q++) {
            const float phi = wts[(l * 4 + q) * 3 + 0];
            const float th  = wts[(l * 4 + q) * 3 + 1];
            const float om  = wts[(l * 4 + q) * 3 + 2];
            const float ct = cosf(0.5f * th), st = sinf(0.5f * th);
            float spo, cpo; sincosf(0.5f * (phi + om), &spo, &cpo);
            float smo, cmo; sincosf(0.5f * (phi - om), &smo, &cmo);
            float* g = rot + (l * 4 + q) * 8;
            g[0] =  cpo * ct; g[1] = -spo * ct;
            g[2] = -cmo * st; g[3] = -smo * st;
            g[4] =  cmo * st; g[5] = -smo * st;
            g[6] =  cpo * ct; g[7] =  spo * ct;
        }
    }

    const float* a = g_ang + (size_t)t * 8;
    float zq[4];
    vqc_eval(a[0], a[1], a[2], a[3], rot, zq);
    /* pre-scale Q by log2(e): scores then use ex2 directly */
    float* qo = g_Qv + (size_t)t * 4;
#pragma unroll
    for (int j = 0; j < 4; j++) qo[j] = zq[j] * 1.4426950408889634f;
    vqc_eval(a[4], a[5], a[6], a[7], rot, g_Kv + (size_t)t * 4);
}

/* =====================  3) V transpose -> fp16, k(t)-permuted in 16-blocks ===================== */
__global__ void __launch_bounds__(256) transpose_kernel(const float* __restrict__ emb)
{
    __shared__ float tile[32][33];
    const int b  = blockIdx.z;
    const int t0 = blockIdx.x * 32;
    const int h0 = blockIdx.y * 32;
    const int tid = threadIdx.y * 32 + threadIdx.x;
    const int tx = threadIdx.x, ty = threadIdx.y;

#pragma unroll
    for (int j = 0; j < 4; j++)
        tile[ty + j * 8][tx] = emb[((size_t)b * SS + t0 + ty + j * 8) * HH + h0 + tx];
    __syncthreads();

    const int hy = tid & 31;
    const int q  = tid >> 5;
    const int blk = q >> 2;
    const int tq  = q & 3;

    const int base = blk * 16;
    __half h[4];
    h[0] = __float2half_rn(tile[base + 2 * tq][hy]);
    h[1] = __float2half_rn(tile[base + 2 * tq + 1][hy]);
    h[2] = __float2half_rn(tile[base + 2 * tq + 8][hy]);
    h[3] = __float2half_rn(tile[base + 2 * tq + 9][hy]);

    *(uint2*)(g_Vth + ((size_t)b * HH + h0 + hy) * SS + t0 + base + 4 * tq) = *(uint2*)h;
}

/* =====================  4) P = exp(Qv Kv^T): 64 rows/CTA, warp-uniform key segment ===================== */
__global__ void __launch_bounds__(256) scoreexp_kernel()
{
    __shared__ float4 sKv[SS];          /* 32 KB */
    __shared__ float sRs[256];
    const int b   = blockIdx.y;
    const int tid = threadIdx.x;
    const int row = tid & 63;
    const int sub = tid >> 6;           /* 0..3: 512 keys each */
    const int s   = blockIdx.x * 64 + row;

    const float4* Kvb = (const float4*)(g_Kv + (size_t)b * SS * 4);
#pragma unroll
    for (int j = 0; j < 8; j++) sKv[tid + j * 256] = Kvb[tid + j * 256];
    __syncthreads();

    const float4 qv = ((const float4*)g_Qv)[(size_t)b * SS + s];   /* pre-scaled by log2e */
    __half* Prow = g_Ph + ((size_t)b * SS + s) * SS;
    float rsum = 0.f;

#pragma unroll 2
    for (int kb = 0; kb < 32; kb++) {
        const int base = sub * 512 + kb * 16;
        float e[16];
#pragma unroll
        for (int j = 0; j < 16; j++) {
            float4 kv = sKv[base + j];          /* warp-uniform address: broadcast */
            e[j] = ex2f(qv.x * kv.x + qv.y * kv.y + qv.z * kv.z + qv.w * kv.w);
        }
#pragma unroll
        for (int j = 0; j < 16; j++) rsum += e[j];
        /* k-permuted fp16 pack: pos 4t+{0,1,2,3} <- e{2t,2t+1,2t+8,2t+9} */
        __half2 h2[8];
        h2[0] = __floats2half2_rn(e[0],  e[1]);
        h2[1] = __floats2half2_rn(e[8],  e[9]);
        h2[2] = __floats2half2_rn(e[2],  e[3]);
        h2[3] = __floats2half2_rn(e[10], e[11]);
        h2[4] = __floats2half2_rn(e[4],  e[5]);
        h2[5] = __floats2half2_rn(e[12], e[13]);
        h2[6] = __floats2half2_rn(e[6],  e[7]);
        h2[7] = __floats2half2_rn(e[14], e[15]);
        uint4* dst = (uint4*)(Prow + base);
        dst[0] = *(uint4*)&h2[0];
        dst[1] = *(uint4*)&h2[4];
    }

    sRs[tid] = rsum;
    __syncthreads();
    if (tid < 64) {
        const float r = sRs[tid] + sRs[tid + 64] + sRs[tid + 128] + sRs[tid + 192];
        g_rinv[(size_t)b * SS + blockIdx.x * 64 + tid] = 1.0f / r;
    }
}

/* =====================  5) fp16 mma.sync GEMM (fp32 acc, 4-stage, 1 barrier/chunk) ===================== */
#define GM 128
#define GN 128
#define GK 32                     /* halves per k-chunk */
#define NCH (SS / GK)             /* 64 */
#define PITCH 40                  /* halves per smem row: 32 data + 8 pad */
#define A_HALVES (GM * PITCH)     /* 5120 (10240 B) */
#define B_HALVES (GN * PITCH)     /* 5120 (10240 B) */
#define STAGE_HALVES (A_HALVES + B_HALVES)   /* 10240 halves = 20480 B */
#define STAGES 4                  /* 4 buffers, 3 chunks in flight */
#define GTHREADS 128

__device__ __forceinline__ void load_chunk(uint32_t sA, uint32_t sB,
                                           const __half* __restrict__ Pb,
                                           const __half* __restrict__ Vtb,
                                           int m0, int n0, int k0, int tid)
{
#pragma unroll
    for (int j = 0; j < 4; j++) {                    /* A: 128 rows x 4 x 16B */
        const int cid = tid + j * GTHREADS;
        const int r = cid >> 2, c = cid & 3;
        cpasync16(sA + (r * PITCH + c * 8) * 2, Pb + (size_t)(m0 + r) * SS + k0 + c * 8);
    }
#pragma unroll
    for (int j = 0; j < 4; j++) {                    /* B: 128 rows x 4 x 16B */
        const int cid = tid + j * GTHREADS;
        const int r = cid >> 2, c = cid & 3;
        cpasync16(sB + (r * PITCH + c * 8) * 2, Vtb + (size_t)(n0 + r) * SS + k0 + c * 8);
    }
    cp_commit();
}

__global__ void __launch_bounds__(GTHREADS, 2) gemm_kernel(float* __restrict__ out)
{
    extern __shared__ __align__(16) __half hsm[];
    const uint32_t smem_base = smem_u32(hsm);
    const int tid  = threadIdx.x;
    const int wid  = tid >> 5;
    const int lane = tid & 31;
    const int g = lane >> 2;
    const int t = lane & 3;

    const int wm = wid & 1;           /* 64-row block */
    const int wn = (wid >> 1) & 1;    /* 64-col block */

    const int b  = blockIdx.y;
    const int nt = blockIdx.x % 6;
    const int mt = blockIdx.x / 6;
    const int m0 = mt * GM;
    const int n0 = nt * GN;

    const __half* Pb  = g_Ph  + (size_t)b * SS * SS;
    const __half* Vtb = g_Vth + (size_t)b * HH * SS;

    float acc[4][8][4];
#pragma unroll
    for (int i = 0; i < 4; i++)
#pragma unroll
        for (int j = 0; j < 8; j++)
#pragma unroll
            for (int k = 0; k < 4; k++) acc[i][j][k] = 0.f;

    const int aBase = (wm * 64 + g) * PITCH + 4 * t;
    const int bBase = (wn * 64 + g) * PITCH + 4 * t;

    /* prologue: 3 chunks in flight */
#pragma unroll
    for (int i = 0; i < 3; i++)
        load_chunk(smem_base + (i * STAGE_HALVES) * 2,
                   smem_base + (i * STAGE_HALVES + A_HALVES) * 2,
                   Pb, Vtb, m0, n0, i * GK, tid);

    for (int i = 0; i < NCH; i++) {
        if (i < NCH - 2)       cp_wait<2>();
        else if (i == NCH - 2) cp_wait<1>();
        else                   cp_wait<0>();
        __syncthreads();   /* chunk i visible; all consumers of stage (i+3)&3 done (iter i-1) */

        if (i + 3 < NCH) {
            const int st = (i + 3) & 3;
            load_chunk(smem_base + (st * STAGE_HALVES) * 2,
                       smem_base + (st * STAGE_HALVES + A_HALVES) * 2,
                       Pb, Vtb, m0, n0, (i + 3) * GK, tid);
        }

        const __half* sA = hsm + (i & 3) * STAGE_HALVES;
        const __half* sB = sA + A_HALVES;

#pragma unroll
        for (int ks = 0; ks < 2; ks++) {
            uint2 aG[4], aG8[4], bF[8];
#pragma unroll
            for (int ti = 0; ti < 4; ti++) {
                aG[ti]  = *(const uint2*)(sA + aBase + ti * 16 * PITCH + ks * 16);
                aG8[ti] = *(const uint2*)(sA + aBase + (ti * 16 + 8) * PITCH + ks * 16);
            }
#pragma unroll
            for (int tj = 0; tj < 8; tj++)
                bF[tj] = *(const uint2*)(sB + bBase + tj * 8 * PITCH + ks * 16);
#pragma unroll
            for (int ti = 0; ti < 4; ti++)
#pragma unroll
                for (int tj = 0; tj < 8; tj++)
                    mma_f16(acc[ti][tj][0], acc[ti][tj][1], acc[ti][tj][2], acc[ti][tj][3],
                            aG[ti].x, aG8[ti].x, aG[ti].y, aG8[ti].y,
                            bF[tj].x, bF[tj].y);
        }
        /* no trailing sync: next overwrite of this stage happens at iter i+1 top,
           after the barrier there orders all consumers of it */
    }

    /* epilogue */
    const float* rinvB = g_rinv + (size_t)b * SS + m0 + wm * 64;
    float* outB = out + ((size_t)b * SS + m0 + wm * 64) * HH + n0 + wn * 64;
#pragma unroll
    for (int ti = 0; ti < 4; ti++) {
        const int r0 = ti * 16 + g;
        const float ri0 = rinvB[r0];
        const float ri1 = rinvB[r0 + 8];
#pragma unroll
        for (int tj = 0; tj < 8; tj++) {
            const int c0 = tj * 8 + 2 * t;
            float2 v0 = make_float2(acc[ti][tj][0] * ri0, acc[ti][tj][1] * ri0);
            float2 v1 = make_float2(acc[ti][tj][2] * ri1, acc[ti][tj][3] * ri1);
            *(float2*)(outB + (size_t)r0 * HH + c0) = v0;
            *(float2*)(outB + (size_t)(r0 + 8) * HH + c0) = v1;
        }
    }
}

/* =====================  launch (single stream, serial — as round 7) ===================== */
extern "C" void kernel_launch(void* const* d_in, const int* in_sizes, int n_in,
                              void* d_out, int out_size)
{
    const float* emb = (const float*)d_in[0];
    const float* Wq  = (const float*)d_in[1];
    const float* bq  = (const float*)d_in[2];
    const float* Wk  = (const float*)d_in[3];
    const float* bk  = (const float*)d_in[4];
    const float* wts = (const float*)d_in[5];
    float* out = (float*)d_out;

    proj_kernel<<<NT / 8, 256>>>(emb, Wq, bq, Wk, bk);
    vqc_kernel<<<NT / 128, 128>>>(wts);
    transpose_kernel<<<dim3(SS / 32, HH / 32, BB), dim3(32, 8)>>>(emb);
    scoreexp_kernel<<<dim3(SS / 64, BB), 256>>>();

    const int smem = STAGES * STAGE_HALVES * 2;          /* 81920 B */
    cudaFuncSetAttribute(gemm_kernel, cudaFuncAttributeMaxDynamicSharedMemorySize, smem);
    gemm_kernel<<<dim3((SS / GM) * (HH / GN), BB), GTHREADS, smem>>>(out);
}

// round 14
// speedup vs baseline: 1.5606x; 1.0451x over previous
#include <cuda_runtime.h>
#include <cuda_fp16.h>
#include <math.h>
#include <stdint.h>

#define BB 8
#define SS 2048
#define HH 768
#define NT (BB*SS)

/* ---------------- device scratch (no allocations allowed) ---------------- */
__device__ float g_ang[NT * 8];
__device__ float g_Qv[NT * 4];     /* pre-scaled by log2(e) */
__device__ float g_Kv[NT * 4];
__device__ float g_rinv[NT];
__device__ __align__(16) __half g_Ph[(size_t)BB * SS * SS];   /* 67 MB: exp(Qv.Kv^T), k-permuted fp16 */

/* ---------------- helpers ---------------- */
__device__ __forceinline__ uint32_t smem_u32(const void* p) {
    uint32_t a;
    asm("{ .reg .u64 t; cvta.to.shared.u64 t, %1; cvt.u32.u64 %0, t; }" : "=r"(a) : "l"(p));
    return a;
}
__device__ __forceinline__ float ex2f(float x) {
    float y; asm("ex2.approx.ftz.f32 %0, %1;" : "=f"(y) : "f"(x)); return y;
}
__device__ __forceinline__ void cpasync16(uint32_t dst, const void* src) {
    asm volatile("cp.async.cg.shared.global [%0], [%1], 16;" :: "r"(dst), "l"(src) : "memory");
}
__device__ __forceinline__ void cp_commit() { asm volatile("cp.async.commit_group;" ::: "memory"); }
template <int N> __device__ __forceinline__ void cp_wait() {
    asm volatile("cp.async.wait_group %0;" :: "n"(N) : "memory");
}
/* fp32-accumulate fp16 mma */
__device__ __forceinline__ void mma_f16(float& c0, float& c1, float& c2, float& c3,
                                        uint32_t a0, uint32_t a1, uint32_t a2, uint32_t a3,
                                        uint32_t b0, uint32_t b1)
{
    asm volatile(
        "mma.sync.aligned.m16n8k16.row.col.f32.f16.f16.f32 "
        "{%0,%1,%2,%3}, {%4,%5,%6,%7}, {%8,%9}, {%0,%1,%2,%3};"
        : "+f"(c0), "+f"(c1), "+f"(c2), "+f"(c3)
        : "r"(a0), "r"(a1), "r"(a2), "r"(a3), "r"(b0), "r"(b1));
}

/* =====================  1) Q/K projection: warp per token ===================== */
__global__ void __launch_bounds__(256) proj_kernel(
    const float* __restrict__ emb,
    const float* __restrict__ Wq, const float* __restrict__ bq,
    const float* __restrict__ Wk, const float* __restrict__ bk)
{
    const int w    = (blockIdx.x * blockDim.x + threadIdx.x) >> 5;
    const int lane = threadIdx.x & 31;

    const float4* e  = (const float4*)(emb + (size_t)w * HH);
    const float4* wq = (const float4*)Wq;
    const float4* wk = (const float4*)Wk;

    float acc[8];
#pragma unroll
    for (int j = 0; j < 8; j++) acc[j] = 0.f;

#pragma unroll
    for (int k = 0; k < 6; k++) {
        const int idx = lane + 32 * k;
        float4 ev = e[idx];
#pragma unroll
        for (int q = 0; q < 4; q++) {
            float4 a = wq[q * 192 + idx];
            acc[q]     += ev.x * a.x + ev.y * a.y + ev.z * a.z + ev.w * a.w;
            float4 c = wk[q * 192 + idx];
            acc[4 + q] += ev.x * c.x + ev.y * c.y + ev.z * c.z + ev.w * c.w;
        }
    }
#pragma unroll
    for (int off = 16; off > 0; off >>= 1)
#pragma unroll
        for (int j = 0; j < 8; j++) acc[j] += __shfl_xor_sync(0xffffffffu, acc[j], off);

    if (lane == 0) {
        float* dst = g_ang + (size_t)w * 8;
#pragma unroll
        for (int q = 0; q < 4; q++) {
            dst[q]     = acc[q] + bq[q];
            dst[4 + q] = acc[4 + q] + bk[q];
        }
    }
}

/* =====================  2) VQC: thread per token ===================== */
__device__ __forceinline__ void vqc_eval(float x0, float x1, float x2, float x3,
                                         const float* rot, float* outz)
{
    float c[4], s[4];
    c[0] = cosf(0.5f * x0); s[0] = sinf(0.5f * x0);
    c[1] = cosf(0.5f * x1); s[1] = sinf(0.5f * x1);
    c[2] = cosf(0.5f * x2); s[2] = sinf(0.5f * x2);
    c[3] = cosf(0.5f * x3); s[3] = sinf(0.5f * x3);

    float pr[16], pi[16];
#pragma unroll
    for (int bb = 0; bb < 16; bb++) {
        float m = ((bb & 8) ? s[0] : c[0]) * ((bb & 4) ? s[1] : c[1]) *
                  ((bb & 2) ? s[2] : c[2]) * ((bb & 1) ? s[3] : c[3]);
        const int k = __popc(bb) & 3;
        pr[bb] = (k == 0) ? m : ((k == 2) ? -m : 0.f);
        pi[bb] = (k == 1) ? -m : ((k == 3) ? m : 0.f);
    }

#pragma unroll
    for (int l = 0; l < 2; l++) {
#pragma unroll
        for (int q = 0; q < 4; q++) {
            const float* g = rot + (l * 4 + q) * 8;
            const float ar = g[0], ai = g[1], br = g[2], bi = g[3];
            const float cr = g[4], ci = g[5], dr = g[6], di = g[7];
            const int mask = 8 >> q;
#pragma unroll
            for (int b0 = 0; b0 < 16; b0++) {
                if (!(b0 & mask)) {
                    const int b1 = b0 | mask;
                    float p0r = pr[b0], p0i = pi[b0], p1r = pr[b1], p1i = pi[b1];
                    pr[b0] = ar * p0r - ai * p0i + br * p1r - bi * p1i;
                    pi[b0] = ar * p0i + ai * p0r + br * p1i + bi * p1r;
                    pr[b1] = cr * p0r - ci * p0i + dr * p1r - di * p1i;
                    pi[b1] = cr * p0i + ci * p0r + dr * p1i + di * p1r;
                }
            }
        }
        const int r = (l % 3) + 1;
#pragma unroll
        for (int i = 0; i < 4; i++) {
            const int cm = 8 >> i;
            const int tm = 8 >> ((i + r) & 3);
#pragma unroll
            for (int b0 = 0; b0 < 16; b0++) {
                if ((b0 & cm) && !(b0 & tm)) {
                    const int b1 = b0 | tm;
                    float tr = pr[b0]; pr[b0] = pr[b1]; pr[b1] = tr;
                    float ti = pi[b0]; pi[b0] = pi[b1]; pi[b1] = ti;
                }
            }
        }
    }

    float z0 = 0.f, z1 = 0.f, z2 = 0.f, z3 = 0.f;
#pragma unroll
    for (int bb = 0; bb < 16; bb++) {
        const float p = pr[bb] * pr[bb] + pi[bb] * pi[bb];
        z0 += (bb & 8) ? -p : p;
        z1 += (bb & 4) ? -p : p;
        z2 += (bb & 2) ? -p : p;
        z3 += (bb & 1) ? -p : p;
    }
    outz[0] = z0; outz[1] = z1; outz[2] = z2; outz[3] = z3;
}

__global__ void __launch_bounds__(128) vqc_kernel(const float* __restrict__ wts)
{
    const int t = blockIdx.x * blockDim.x + threadIdx.x;

    float rot[64];
#pragma unroll
    for (int l = 0; l < 2; l++) {
#pragma unroll
        for (int q = 0; q < 4; q++) {
            const float phi = wts[(l * 4 + q) * 3 + 0];
            const float th  = wts[(l * 4 + q) * 3 + 1];
            const float om  = wts[(l * 4 + q) * 3 + 2];
            const float ct = cosf(0.5f * th), st = sinf(0.5f * th);
            float spo, cpo; sincosf(0.5f * (phi + om), &spo, &cpo);
            float smo, cmo; sincosf(0.5f * (phi - om), &smo, &cmo);
            float* g = rot + (l * 4 + q) * 8;
            g[0] =  cpo * ct; g[1] = -spo * ct;
            g[2] = -cmo * st; g[3] = -smo * st;
            g[4] =  cmo * st; g[5] = -smo * st;
            g[6] =  cpo * ct; g[7] =  spo * ct;
        }
    }

    const float* a = g_ang + (size_t)t * 8;
    float zq[4];
    vqc_eval(a[0], a[1], a[2], a[3], rot, zq);
    /* pre-scale Q by log2(e): scores then use ex2 directly */
    float* qo = g_Qv + (size_t)t * 4;
#pragma unroll
    for (int j = 0; j < 4; j++) qo[j] = zq[j] * 1.4426950408889634f;
    vqc_eval(a[4], a[5], a[6], a[7], rot, g_Kv + (size_t)t * 4);
}

/* =====================  3) P = exp(Qv Kv^T): 64 rows/CTA, warp-uniform key segment ===================== */
__global__ void __launch_bounds__(256) scoreexp_kernel()
{
    __shared__ float4 sKv[SS];          /* 32 KB */
    __shared__ float sRs[256];
    const int b   = blockIdx.y;
    const int tid = threadIdx.x;
    const int row = tid & 63;
    const int sub = tid >> 6;           /* 0..3: 512 keys each */
    const int s   = blockIdx.x * 64 + row;

    const float4* Kvb = (const float4*)(g_Kv + (size_t)b * SS * 4);
#pragma unroll
    for (int j = 0; j < 8; j++) sKv[tid + j * 256] = Kvb[tid + j * 256];
    __syncthreads();

    const float4 qv = ((const float4*)g_Qv)[(size_t)b * SS + s];   /* pre-scaled by log2e */
    __half* Prow = g_Ph + ((size_t)b * SS + s) * SS;
    float rsum = 0.f;

#pragma unroll 2
    for (int kb = 0; kb < 32; kb++) {
        const int base = sub * 512 + kb * 16;
        float e[16];
#pragma unroll
        for (int j = 0; j < 16; j++) {
            float4 kv = sKv[base + j];          /* warp-uniform address: broadcast */
            e[j] = ex2f(qv.x * kv.x + qv.y * kv.y + qv.z * kv.z + qv.w * kv.w);
        }
#pragma unroll
        for (int j = 0; j < 16; j++) rsum += e[j];
        /* k-permuted fp16 pack: pos 4t+{0,1,2,3} <- e{2t,2t+1,2t+8,2t+9} */
        __half2 h2[8];
        h2[0] = __floats2half2_rn(e[0],  e[1]);
        h2[1] = __floats2half2_rn(e[8],  e[9]);
        h2[2] = __floats2half2_rn(e[2],  e[3]);
        h2[3] = __floats2half2_rn(e[10], e[11]);
        h2[4] = __floats2half2_rn(e[4],  e[5]);
        h2[5] = __floats2half2_rn(e[12], e[13]);
        h2[6] = __floats2half2_rn(e[6],  e[7]);
        h2[7] = __floats2half2_rn(e[14], e[15]);
        uint4* dst = (uint4*)(Prow + base);
        dst[0] = *(uint4*)&h2[0];
        dst[1] = *(uint4*)&h2[4];
    }

    sRs[tid] = rsum;
    __syncthreads();
    if (tid < 64) {
        const float r = sRs[tid] + sRs[tid + 64] + sRs[tid + 128] + sRs[tid + 192];
        g_rinv[(size_t)b * SS + blockIdx.x * 64 + tid] = 1.0f / r;
    }
}

/* =====================  4) fused GEMM: O = (P @ V) * rinv, V read raw fp32 from emb ===================== */
/* A (P) fp16 k-permuted in smem; B (V) fp32 t-major in smem, transposed+converted at
   fragment-build time (4x LDS.32 + 2x cvt per fragment, true-k order matching A). */
#define GM 128
#define GN 128
#define GK 32                       /* k (tokens) per chunk */
#define NCH (SS / GK)               /* 64 */
#define PITCH 40                    /* A smem: halves per row (32 data + 8 pad) */
#define A_HALVES (GM * PITCH)       /* 5120 halves = 10240 B */
#define BPITCH 132                  /* B smem: floats per row (128 data + 4 pad) -> conflict-free frag reads */
#define B_FLOATS (GK * BPITCH)      /* 4224 floats = 16896 B */
#define STAGE_BYTES (A_HALVES * 2 + B_FLOATS * 4)   /* 27136 B */
#define STAGES 3
#define GTHREADS 128

__device__ __forceinline__ void load_chunk(uint32_t sA, uint32_t sB,
                                           const __half* __restrict__ Pb,
                                           const float* __restrict__ Vb,
                                           int m0, int n0, int k0, int tid)
{
#pragma unroll
    for (int j = 0; j < 4; j++) {                    /* A: 128 rows x 4 x 16B (fp16) */
        const int cid = tid + j * GTHREADS;
        const int r = cid >> 2, c = cid & 3;
        cpasync16(sA + (r * PITCH + c * 8) * 2, Pb + (size_t)(m0 + r) * SS + k0 + c * 8);
    }
#pragma unroll
    for (int j = 0; j < 8; j++) {                    /* B: 32 rows x 32 x 16B (fp32) */
        const int cid = tid + j * GTHREADS;
        const int r = cid >> 5, c = cid & 31;
        cpasync16(sB + r * (BPITCH * 4) + c * 16,
                  Vb + (size_t)(k0 + r) * HH + n0 + c * 4);
    }
    cp_commit();
}

__global__ void __launch_bounds__(GTHREADS, 2) gemm_kernel(const float* __restrict__ emb,
                                                           float* __restrict__ out)
{
    extern __shared__ __align__(16) char dsm[];
    const uint32_t smem_base = smem_u32(dsm);
    const int tid  = threadIdx.x;
    const int wid  = tid >> 5;
    const int lane = tid & 31;
    const int g = lane >> 2;
    const int t = lane & 3;

    const int wm = wid & 1;           /* 64-row block */
    const int wn = (wid >> 1) & 1;    /* 64-col block */

    const int b  = blockIdx.y;
    const int nt = blockIdx.x % 6;
    const int mt = blockIdx.x / 6;
    const int m0 = mt * GM;
    const int n0 = nt * GN;

    const __half* Pb = g_Ph + (size_t)b * SS * SS;
    const float*  Vb = emb  + (size_t)b * SS * HH;

    float acc[4][8][4];
#pragma unroll
    for (int i = 0; i < 4; i++)
#pragma unroll
        for (int j = 0; j < 8; j++)
#pragma unroll
            for (int k = 0; k < 4; k++) acc[i][j][k] = 0.f;

    const int aBase = (wm * 64 + g) * PITCH + 4 * t;
    /* B fragment base: column n = wn*64 + tj*8 + g; rows 2t, 2t+1, 2t+8, 2t+9 (+16 for ks=1) */
    const int bColBase = wn * 64 + g;

    load_chunk(smem_base, smem_base + A_HALVES * 2, Pb, Vb, m0, n0, 0, tid);
    load_chunk(smem_base + STAGE_BYTES, smem_base + STAGE_BYTES + A_HALVES * 2,
               Pb, Vb, m0, n0, GK, tid);

    for (int i = 0; i < NCH; i++) {
        if (i + 2 < NCH) cp_wait<1>(); else cp_wait<0>();
        __syncthreads();

        if (i + 2 < NCH) {
            const int st = (i + 2) % STAGES;
            load_chunk(smem_base + st * STAGE_BYTES,
                       smem_base + st * STAGE_BYTES + A_HALVES * 2,
                       Pb, Vb, m0, n0, (i + 2) * GK, tid);
        }

        const __half* sA = (const __half*)(dsm + (i % STAGES) * STAGE_BYTES);
        const float*  sB = (const float*)(dsm + (i % STAGES) * STAGE_BYTES + A_HALVES * 2);

#pragma unroll
        for (int ks = 0; ks < 2; ks++) {
            uint2 aG[4], aG8[4];
#pragma unroll
            for (int ti = 0; ti < 4; ti++) {
                aG[ti]  = *(const uint2*)(sA + aBase + ti * 16 * PITCH + ks * 16);
                aG8[ti] = *(const uint2*)(sA + aBase + (ti * 16 + 8) * PITCH + ks * 16);
            }
            /* build B fragments from raw fp32 V tile (transpose + cvt) */
            uint32_t bF0[8], bF1[8];
            const float* colp = sB + (ks * 16 + 2 * t) * BPITCH + bColBase;
#pragma unroll
            for (int tj = 0; tj < 8; tj++) {
                const float* cp2 = colp + tj * 8;
                float v0 = cp2[0];
                float v1 = cp2[BPITCH];
                float v2 = cp2[8 * BPITCH];
                float v3 = cp2[9 * BPITCH];
                __half2 h0 = __floats2half2_rn(v0, v1);
                __half2 h1 = __floats2half2_rn(v2, v3);
                bF0[tj] = *(uint32_t*)&h0;
                bF1[tj] = *(uint32_t*)&h1;
            }
#pragma unroll
            for (int ti = 0; ti < 4; ti++)
#pragma unroll
                for (int tj = 0; tj < 8; tj++)
                    mma_f16(acc[ti][tj][0], acc[ti][tj][1], acc[ti][tj][2], acc[ti][tj][3],
                            aG[ti].x, aG8[ti].x, aG[ti].y, aG8[ti].y,
                            bF0[tj], bF1[tj]);
        }
        __syncthreads();
    }

    /* epilogue */
    const float* rinvB = g_rinv + (size_t)b * SS + m0 + wm * 64;
    float* outB = out + ((size_t)b * SS + m0 + wm * 64) * HH + n0 + wn * 64;
#pragma unroll
    for (int ti = 0; ti < 4; ti++) {
        const int r0 = ti * 16 + g;
        const float ri0 = rinvB[r0];
        const float ri1 = rinvB[r0 + 8];
#pragma unroll
        for (int tj = 0; tj < 8; tj++) {
            const int c0 = tj * 8 + 2 * t;
            float2 v0 = make_float2(acc[ti][tj][0] * ri0, acc[ti][tj][1] * ri0);
            float2 v1 = make_float2(acc[ti][tj][2] * ri1, acc[ti][tj][3] * ri1);
            *(float2*)(outB + (size_t)r0 * HH + c0) = v0;
            *(float2*)(outB + (size_t)(r0 + 8) * HH + c0) = v1;
        }
    }
}

/* =====================  launch ===================== */
extern "C" void kernel_launch(void* const* d_in, const int* in_sizes, int n_in,
                              void* d_out, int out_size)
{
    const float* emb = (const float*)d_in[0];
    const float* Wq  = (const float*)d_in[1];
    const float* bq  = (const float*)d_in[2];
    const float* Wk  = (const float*)d_in[3];
    const float* bk  = (const float*)d_in[4];
    const float* wts = (const float*)d_in[5];
    float* out = (float*)d_out;

    proj_kernel<<<NT / 8, 256>>>(emb, Wq, bq, Wk, bk);
    vqc_kernel<<<NT / 128, 128>>>(wts);
    scoreexp_kernel<<<dim3(SS / 64, BB), 256>>>();

    const int smem = STAGES * STAGE_BYTES;               /* 81408 B */
    cudaFuncSetAttribute(gemm_kernel, cudaFuncAttributeMaxDynamicSharedMemorySize, smem);
    gemm_kernel<<<dim3((SS / GM) * (HH / GN), BB), GTHREADS, smem>>>(emb, out);
}